// round 6
// baseline (speedup 1.0000x reference)
#include <cuda_runtime.h>
#include <cstdint>

#define NB   16
#define NN   20000
#define NE   640000
#define NREG 2000
#define DIN  128
#define FF   32

// ---------------- scratch (device globals; no allocation allowed) ----------
__device__ float    g_h[(size_t)NB * NN * FF];       // 40.96 MB
__device__ float    g_hsrc[(size_t)NB * NREG * FF];  // 4.1 MB (hot gather set)
__device__ float    g_rep[(size_t)NB * NN * FF];     // 40.96 MB
__device__ float    g_Wt[FF * DIN];                  // W transposed [f][k]
__device__ float    g_asrc[NB * NN];
__device__ float    g_adst[NB * NN];
__device__ int      g_src32[NE];
__device__ int      g_dst32[NE];
__device__ int      g_cnt[NN];
__device__ int      g_off[NN + 1];
__device__ int      g_cur[NN];
__device__ unsigned g_sorted[NE];                    // (src<<20)|eid
__device__ int      g_soff[NREG + 1];
__device__ float    g_meanpart[NB][8];
__device__ float    g_mean[NB];
__device__ float    g_c;
__device__ int      g_is64;

// ---------------- f32x2 helpers ---------------------------------------------
__device__ __forceinline__ void fma2(unsigned long long& d,
                                     unsigned long long a,
                                     unsigned long long b) {
    asm("fma.rn.f32x2 %0, %1, %2, %0;" : "+l"(d) : "l"(a), "l"(b));
}
__device__ __forceinline__ unsigned long long dup2(float w) {
    unsigned long long r;
    asm("mov.b64 %0, {%1, %1};" : "=l"(r) : "f"(w));
    return r;
}
__device__ __forceinline__ void unpack2(unsigned long long v, float& lo, float& hi) {
    asm("mov.b64 {%0, %1}, %2;" : "=f"(lo), "=f"(hi) : "l"(v));
}

// ---------------- dtype detection -------------------------------------------
__global__ void k_detect(const int* __restrict__ p) {
    int any = 0;
    for (int i = threadIdx.x; i < 1024; i += 32)
        if ((i & 1) && p[i] != 0) any = 1;
    #pragma unroll
    for (int o = 16; o; o >>= 1) any |= __shfl_xor_sync(0xFFFFFFFFu, any, o);
    if (threadIdx.x == 0) g_is64 = !any;
}

// ---------------- W transpose ------------------------------------------------
__global__ void k_wt(const float* __restrict__ W) {
    int i = blockIdx.x * 256 + threadIdx.x;
    if (i < FF * DIN) {
        int f = i >> 7, k = i & 127;
        g_Wt[i] = W[k * FF + f];
    }
}

// ---------------- prep: zero cnt, mean partials, scalar c -------------------
__global__ void k_prep(const float* __restrict__ eattr,
                       const float* __restrict__ lin_edge,
                       const float* __restrict__ att_edge) {
    int tid = threadIdx.x, bx = blockIdx.x, by = blockIdx.y;
    int lane = tid & 31, wid = tid >> 5;

    int id = (by * 8 + bx) * 256 + tid;
    if (id < NN) g_cnt[id] = 0;

    if (bx == 0 && by == 0 && wid == 1) {
        float p = lin_edge[lane] * att_edge[lane];
        #pragma unroll
        for (int o = 16; o; o >>= 1) p += __shfl_xor_sync(0xFFFFFFFFu, p, o);
        if (lane == 0) g_c = p;
    }

    const float* p = eattr + (size_t)by * NE;
    float s = 0.f;
    for (int i = bx * 256 + tid; i < NE; i += 8 * 256) s += p[i];
    __shared__ float sm[8];
    #pragma unroll
    for (int o = 16; o; o >>= 1) s += __shfl_xor_sync(0xFFFFFFFFu, s, o);
    if (lane == 0) sm[wid] = s;
    __syncthreads();
    if (wid == 0) {
        s = (lane < 8) ? sm[lane] : 0.f;
        #pragma unroll
        for (int o = 4; o; o >>= 1) s += __shfl_xor_sync(0xFFFFFFFFu, s, o);
        if (lane == 0) g_meanpart[by][bx] = s;
    }
}

// ---------------- convert indices + histogram -------------------------------
__global__ void k_convert(const void* __restrict__ srcv,
                          const void* __restrict__ dstv) {
    int e = blockIdx.x * blockDim.x + threadIdx.x;
    if (e >= NE) return;
    int s, d;
    if (g_is64) {
        s = (int)((const long long*)srcv)[e];
        d = (int)((const long long*)dstv)[e];
    } else {
        s = ((const int*)srcv)[e];
        d = ((const int*)dstv)[e];
    }
    g_src32[e] = s;
    g_dst32[e] = d;
    atomicAdd(&g_cnt[d], 1);
}

// ---------------- scan + soff + mean finalize (single block, 1024 thr) ------
__global__ void k_scan() {
    __shared__ int tot[1024];
    int t = threadIdx.x;
    int base = t * 20;
    int loc[20];
    int run = 0;
    #pragma unroll
    for (int i = 0; i < 20; i++) {
        int idx = base + i;
        int v = (idx < NN) ? g_cnt[idx] : 0;
        loc[i] = run;
        run += v;
    }
    tot[t] = run;
    __syncthreads();
    for (int off = 1; off < 1024; off <<= 1) {
        int v = (t >= off) ? tot[t - off] : 0;
        __syncthreads();
        tot[t] += v;
        __syncthreads();
    }
    int excl = tot[t] - run;
    #pragma unroll
    for (int i = 0; i < 20; i++) {
        int idx = base + i;
        if (idx < NN) {
            int o = excl + loc[i];
            g_off[idx] = o;
            g_cur[idx] = o;
        }
    }
    if (t == 1023) g_off[NN] = tot[1023];

    for (int r = t; r <= NREG; r += 1024) {
        int lo = 0, hi = NE;
        while (lo < hi) {
            int mid = (lo + hi) >> 1;
            if (g_src32[mid] < r) lo = mid + 1; else hi = mid;
        }
        g_soff[r] = lo;
    }

    if (t < NB) {
        float s = 0.f;
        #pragma unroll
        for (int i = 0; i < 8; i++) s += g_meanpart[t][i];
        g_mean[t] = s * (1.0f / NE);
    }
}

__global__ void k_scatter() {
    int e = blockIdx.x * blockDim.x + threadIdx.x;
    if (e >= NE) return;
    int d = g_dst32[e];
    int pos = atomicAdd(&g_cur[d], 1);
    g_sorted[pos] = ((unsigned)g_src32[e] << 20) | (unsigned)e;
}

// ---------------- compact hot gather set (src rows < NREG) ------------------
__global__ void k_hsrc() {
    int i = blockIdx.x * 256 + threadIdx.x;   // 0 .. NB*NREG*FF-1
    int b = i / (NREG * FF);
    int w = i - b * (NREG * FF);
    g_hsrc[i] = g_h[(size_t)b * NN * FF + w];
}

// ---------------- GEMM (f32x2 packed): h = x @ W, a_src, a_dst --------------
// W read lane-indexed from L1-resident g_Wt; x staged per-warp in smem.
__global__ void __launch_bounds__(256, 5)
k_gemm(const float* __restrict__ x,
       const float* __restrict__ attS, const float* __restrict__ attD) {
    __shared__ float2 xp[8][4][128];

    int tid = threadIdx.x, wid = tid >> 5, lane = tid & 31;

    size_t rowBase = (size_t)blockIdx.x * 64 + (size_t)wid * 8;
    const float* xg = x + rowBase * DIN;
    #pragma unroll
    for (int p = 0; p < 4; p++) {
        float4 r0 = ((const float4*)(xg + (2 * p + 0) * DIN))[lane];
        float4 r1 = ((const float4*)(xg + (2 * p + 1) * DIN))[lane];
        xp[wid][p][4 * lane + 0] = make_float2(r0.x, r1.x);
        xp[wid][p][4 * lane + 1] = make_float2(r0.y, r1.y);
        xp[wid][p][4 * lane + 2] = make_float2(r0.z, r1.z);
        xp[wid][p][4 * lane + 3] = make_float2(r0.w, r1.w);
    }
    __syncwarp();

    const float4* Wt4 = (const float4*)g_Wt;   // [f][kquad] : 32 x 32
    unsigned long long acc[4] = {0ull, 0ull, 0ull, 0ull};
    #pragma unroll 4
    for (int kc = 0; kc < 32; kc++) {
        float4 wf = __ldg(Wt4 + lane * 32 + kc);
        unsigned long long w0 = dup2(wf.x), w1 = dup2(wf.y);
        unsigned long long w2 = dup2(wf.z), w3 = dup2(wf.w);
        #pragma unroll
        for (int p = 0; p < 4; p++) {
            ulonglong2 u01 = *(const ulonglong2*)&xp[wid][p][4 * kc + 0];
            ulonglong2 u23 = *(const ulonglong2*)&xp[wid][p][4 * kc + 2];
            fma2(acc[p], u01.x, w0);
            fma2(acc[p], u01.y, w1);
            fma2(acc[p], u23.x, w2);
            fma2(acc[p], u23.y, w3);
        }
    }

    float aS = attS[lane], aD = attD[lane];
    float* hp = g_h + rowBase * FF;
    #pragma unroll
    for (int p = 0; p < 4; p++) {
        float lo, hi;
        unpack2(acc[p], lo, hi);
        hp[(2 * p + 0) * FF + lane] = lo;
        hp[(2 * p + 1) * FF + lane] = hi;
        float vs0 = lo * aS, vd0 = lo * aD, vs1 = hi * aS, vd1 = hi * aD;
        #pragma unroll
        for (int o = 16; o; o >>= 1) {
            vs0 += __shfl_xor_sync(0xFFFFFFFFu, vs0, o);
            vd0 += __shfl_xor_sync(0xFFFFFFFFu, vd0, o);
            vs1 += __shfl_xor_sync(0xFFFFFFFFu, vs1, o);
            vd1 += __shfl_xor_sync(0xFFFFFFFFu, vd1, o);
        }
        if (lane == 0) {
            g_asrc[rowBase + 2 * p + 0] = vs0;
            g_adst[rowBase + 2 * p + 0] = vd0;
            g_asrc[rowBase + 2 * p + 1] = vs1;
            g_adst[rowBase + 2 * p + 1] = vd1;
        }
    }
}

// ---------------- single-pass per-(b,dst) softmax + aggregation -------------
__device__ __forceinline__ float lrelu(float a) {
    return fmaxf(a, 0.f) + 0.2f * fminf(a, 0.f);
}

__global__ void __launch_bounds__(256)
k_edge(const float* __restrict__ eattr, const float* __restrict__ bias) {
    int wid = threadIdx.x >> 5, lane = threadIdx.x & 31;
    int seg = blockIdx.x * 8 + wid;                 // 0 .. NB*NN-1
    int b = seg / NN, d = seg - b * NN;

    const float* asb = g_asrc + b * NN;
    const float* eab = eattr + (size_t)b * NE;
    const float* hsb = g_hsrc + (size_t)b * NREG * FF;   // hot 256KB/batch
    float ad = g_adst[b * NN + d];
    float c = g_c;
    int lo = g_off[d], hi = g_off[d + 1];
    int q = lane & 7, g4 = lane >> 3;

    float4 acc0 = make_float4(0.f, 0.f, 0.f, 0.f);
    float4 acc1 = make_float4(0.f, 0.f, 0.f, 0.f);
    float ssum = 0.f;

    for (int base = lo; base < hi; base += 32) {
        int m = hi - base;
        if (m > 32) m = 32;
        float ex = 0.f;
        int idx = 0;                                 // safe row, weight 0
        if (lane < m) {
            unsigned p = __ldcs(&g_sorted[base + lane]);
            int sA = p >> 20;
            int eid = p & 0xFFFFFu;
            ex = __expf(lrelu(asb[sA] + ad + c * __ldcs(&eab[eid])));
            idx = sA * FF;
        }
        ssum += ex;

        // one fully-unrolled pass: 8 independent LDG.128 (rows j = 4t+g4)
        float e[8];
        int   i8[8];
        #pragma unroll
        for (int t = 0; t < 8; t++) {
            int j = 4 * t + g4;
            e[t]  = __shfl_sync(0xFFFFFFFFu, ex, j);
            i8[t] = __shfl_sync(0xFFFFFFFFu, idx, j);
        }
        float4 v[8];
        #pragma unroll
        for (int t = 0; t < 8; t++)
            v[t] = *(const float4*)(hsb + i8[t] + q * 4);
        #pragma unroll
        for (int t = 0; t < 8; t += 2) {
            acc0.x = fmaf(e[t], v[t].x, acc0.x);
            acc0.y = fmaf(e[t], v[t].y, acc0.y);
            acc0.z = fmaf(e[t], v[t].z, acc0.z);
            acc0.w = fmaf(e[t], v[t].w, acc0.w);
            acc1.x = fmaf(e[t + 1], v[t + 1].x, acc1.x);
            acc1.y = fmaf(e[t + 1], v[t + 1].y, acc1.y);
            acc1.z = fmaf(e[t + 1], v[t + 1].z, acc1.z);
            acc1.w = fmaf(e[t + 1], v[t + 1].w, acc1.w);
        }
    }
    acc0.x += acc1.x; acc0.y += acc1.y; acc0.z += acc1.z; acc0.w += acc1.w;

    float exs = __expf(lrelu(asb[d] + ad + c * g_mean[b]));
    #pragma unroll
    for (int o = 16; o; o >>= 1) ssum += __shfl_xor_sync(0xFFFFFFFFu, ssum, o);
    float inv = 1.f / (ssum + exs);

    #pragma unroll
    for (int o = 8; o <= 16; o <<= 1) {
        acc0.x += __shfl_xor_sync(0xFFFFFFFFu, acc0.x, o);
        acc0.y += __shfl_xor_sync(0xFFFFFFFFu, acc0.y, o);
        acc0.z += __shfl_xor_sync(0xFFFFFFFFu, acc0.z, o);
        acc0.w += __shfl_xor_sync(0xFFFFFFFFu, acc0.w, o);
    }

    if (lane < 8) {
        const float4* hsp = (const float4*)(g_h + ((size_t)b * NN + d) * FF + q * 4);
        float4 hs = __ldcs(hsp);                     // self row, read once
        float4 bq = *(const float4*)(bias + q * 4);
        float4 r;
        r.x = fmaf(exs, hs.x, acc0.x) * inv + bq.x;
        r.y = fmaf(exs, hs.y, acc0.y) * inv + bq.y;
        r.z = fmaf(exs, hs.z, acc0.z) * inv + bq.z;
        r.w = fmaf(exs, hs.w, acc0.w) * inv + bq.w;
        *(float4*)(g_rep + ((size_t)b * NN + d) * FF + q * 4) = r;
    }
}

// ---------------- regulon pooling: out[b,r] = rep[b,r] + sum rep[b,dst] -----
__global__ void __launch_bounds__(256)
k_pool(float* __restrict__ out) {
    int wid = threadIdx.x >> 5, lane = threadIdx.x & 31;
    int seg = blockIdx.x * 8 + wid;                 // 0 .. NB*NREG-1
    int b = seg / NREG, r = seg - b * NREG;
    int lo = g_soff[r], hi = g_soff[r + 1];
    const float* repb = g_rep + (size_t)b * NN * FF;
    int q = lane & 7, g4 = lane >> 3;

    float4 a0 = make_float4(0.f, 0.f, 0.f, 0.f);
    float4 a1 = make_float4(0.f, 0.f, 0.f, 0.f);

    for (int base = lo; base < hi; base += 32) {
        int m = hi - base;
        if (m > 32) m = 32;
        int idx = (lane < m) ? __ldcs(&g_dst32[base + lane]) * FF : -1;

        int i8[8];
        #pragma unroll
        for (int t = 0; t < 8; t++)
            i8[t] = __shfl_sync(0xFFFFFFFFu, idx, 4 * t + g4);
        float4 v[8];
        #pragma unroll
        for (int t = 0; t < 8; t++)
            if (i8[t] >= 0) v[t] = *(const float4*)(repb + i8[t] + q * 4);
            else            v[t] = make_float4(0.f, 0.f, 0.f, 0.f);
        #pragma unroll
        for (int t = 0; t < 8; t += 2) {
            a0.x += v[t].x; a0.y += v[t].y; a0.z += v[t].z; a0.w += v[t].w;
            a1.x += v[t + 1].x; a1.y += v[t + 1].y;
            a1.z += v[t + 1].z; a1.w += v[t + 1].w;
        }
    }
    a0.x += a1.x; a0.y += a1.y; a0.z += a1.z; a0.w += a1.w;

    #pragma unroll
    for (int o = 8; o <= 16; o <<= 1) {
        a0.x += __shfl_xor_sync(0xFFFFFFFFu, a0.x, o);
        a0.y += __shfl_xor_sync(0xFFFFFFFFu, a0.y, o);
        a0.z += __shfl_xor_sync(0xFFFFFFFFu, a0.z, o);
        a0.w += __shfl_xor_sync(0xFFFFFFFFu, a0.w, o);
    }

    if (lane < 8) {
        float4 self = *(const float4*)(repb + (size_t)r * FF + q * 4);
        float4 o4;
        o4.x = a0.x + self.x;
        o4.y = a0.y + self.y;
        o4.z = a0.z + self.z;
        o4.w = a0.w + self.w;
        *(float4*)(out + ((size_t)b * NREG + r) * FF + q * 4) = o4;
    }
}

// ---------------- launch ---------------------------------------------------
extern "C" void kernel_launch(void* const* d_in, const int* in_sizes, int n_in,
                              void* d_out, int out_size) {
    const float* x        = (const float*)d_in[0];
    const float* edgeattr = (const float*)d_in[1];
    const float* W        = (const float*)d_in[2];
    const float* att_src  = (const float*)d_in[3];
    const float* att_dst  = (const float*)d_in[4];
    const float* lin_edge = (const float*)d_in[5];
    const float* att_edge = (const float*)d_in[6];
    const float* bias     = (const float*)d_in[7];
    const void*  esrc     = d_in[8];
    const void*  edst     = d_in[9];
    float* out = (float*)d_out;

    k_detect<<<1, 32>>>((const int*)edst);
    k_wt<<<16, 256>>>(W);
    k_prep<<<dim3(8, NB), 256>>>(edgeattr, lin_edge, att_edge);
    k_convert<<<NE / 256, 256>>>(esrc, edst);
    k_gemm<<<(NB * NN) / 64, 256>>>(x, att_src, att_dst);
    k_scan<<<1, 1024>>>();
    k_scatter<<<NE / 256, 256>>>();
    k_hsrc<<<(NB * NREG * FF) / 256, 256>>>();
    k_edge<<<(NB * NN) / 8, 256>>>(edgeattr, bias);
    k_pool<<<(NB * NREG) / 8, 256>>>(out);
}

// round 7
// speedup vs baseline: 1.1642x; 1.1642x over previous
#include <cuda_runtime.h>
#include <cstdint>

#define NB   16
#define NN   20000
#define NE   640000
#define NREG 2000
#define DIN  128
#define FF   32
#define SPLIT 1000   // src-split for L1-resident gather passes (128KB each)

// ---------------- scratch (device globals; no allocation allowed) ----------
__device__ float    g_h[(size_t)NB * NN * FF];       // 40.96 MB
__device__ float    g_rep[(size_t)NB * NN * FF];     // 40.96 MB
__device__ float    g_asrc[NB * NN];
__device__ float    g_adst[NB * NN];
__device__ int      g_src32[NE];
__device__ int      g_dst32[NE];
__device__ int      g_cnt[NN];
__device__ int      g_off[NN + 1];
__device__ int      g_cur[NN];
__device__ unsigned g_sorted[NE];                    // (src<<20)|eid
__device__ int      g_soff[NREG + 1];
__device__ float    g_meanpart[NB][8];
__device__ float    g_mean[NB];
__device__ float    g_c;
__device__ int      g_is64;

// ---------------- f32x2 helpers ---------------------------------------------
__device__ __forceinline__ void fma2(unsigned long long& d,
                                     unsigned long long a,
                                     unsigned long long b) {
    asm("fma.rn.f32x2 %0, %1, %2, %0;" : "+l"(d) : "l"(a), "l"(b));
}
__device__ __forceinline__ unsigned long long dup2(float w) {
    unsigned long long r;
    asm("mov.b64 %0, {%1, %1};" : "=l"(r) : "f"(w));
    return r;
}
__device__ __forceinline__ void unpack2(unsigned long long v, float& lo, float& hi) {
    asm("mov.b64 {%0, %1}, %2;" : "=f"(lo), "=f"(hi) : "l"(v));
}

// ---------------- prep: zero cnt, mean partials, scalar c, dtype detect -----
__global__ void k_prep(const float* __restrict__ eattr,
                       const float* __restrict__ lin_edge,
                       const float* __restrict__ att_edge,
                       const int* __restrict__ edge_raw) {
    int tid = threadIdx.x, bx = blockIdx.x, by = blockIdx.y;
    int lane = tid & 31, wid = tid >> 5;

    int id = (by * 8 + bx) * 256 + tid;
    if (id < NN) g_cnt[id] = 0;

    if (bx == 0 && by == 0) {
        if (wid == 0) {
            // dtype detect: int64 values < 2^31 => all odd int32 words zero
            int any = 0;
            for (int i = lane; i < 1024; i += 32)
                if ((i & 1) && edge_raw[i] != 0) any = 1;
            #pragma unroll
            for (int o = 16; o; o >>= 1) any |= __shfl_xor_sync(0xFFFFFFFFu, any, o);
            if (lane == 0) g_is64 = !any;
        } else if (wid == 1) {
            float p = lin_edge[lane] * att_edge[lane];
            #pragma unroll
            for (int o = 16; o; o >>= 1) p += __shfl_xor_sync(0xFFFFFFFFu, p, o);
            if (lane == 0) g_c = p;
        }
    }

    const float* p = eattr + (size_t)by * NE;
    float s = 0.f;
    for (int i = bx * 256 + tid; i < NE; i += 8 * 256) s += p[i];
    __shared__ float sm[8];
    #pragma unroll
    for (int o = 16; o; o >>= 1) s += __shfl_xor_sync(0xFFFFFFFFu, s, o);
    if (lane == 0) sm[wid] = s;
    __syncthreads();
    if (wid == 0) {
        s = (lane < 8) ? sm[lane] : 0.f;
        #pragma unroll
        for (int o = 4; o; o >>= 1) s += __shfl_xor_sync(0xFFFFFFFFu, s, o);
        if (lane == 0) g_meanpart[by][bx] = s;
    }
}

// ---------------- convert indices + histogram -------------------------------
__global__ void k_convert(const void* __restrict__ srcv,
                          const void* __restrict__ dstv) {
    int e = blockIdx.x * blockDim.x + threadIdx.x;
    if (e >= NE) return;
    int s, d;
    if (g_is64) {
        s = (int)((const long long*)srcv)[e];
        d = (int)((const long long*)dstv)[e];
    } else {
        s = ((const int*)srcv)[e];
        d = ((const int*)dstv)[e];
    }
    g_src32[e] = s;
    g_dst32[e] = d;
    atomicAdd(&g_cnt[d], 1);
}

// ---------------- scan + soff + mean finalize (single block, 1024 thr) ------
__global__ void k_scan() {
    __shared__ int tot[1024];
    int t = threadIdx.x;
    int base = t * 20;
    int loc[20];
    int run = 0;
    #pragma unroll
    for (int i = 0; i < 20; i++) {
        int idx = base + i;
        int v = (idx < NN) ? g_cnt[idx] : 0;
        loc[i] = run;
        run += v;
    }
    tot[t] = run;
    __syncthreads();
    for (int off = 1; off < 1024; off <<= 1) {
        int v = (t >= off) ? tot[t - off] : 0;
        __syncthreads();
        tot[t] += v;
        __syncthreads();
    }
    int excl = tot[t] - run;
    #pragma unroll
    for (int i = 0; i < 20; i++) {
        int idx = base + i;
        if (idx < NN) {
            int o = excl + loc[i];
            g_off[idx] = o;
            g_cur[idx] = o;
        }
    }
    if (t == 1023) g_off[NN] = tot[1023];

    for (int r = t; r <= NREG; r += 1024) {
        int lo = 0, hi = NE;
        while (lo < hi) {
            int mid = (lo + hi) >> 1;
            if (g_src32[mid] < r) lo = mid + 1; else hi = mid;
        }
        g_soff[r] = lo;
    }

    if (t < NB) {
        float s = 0.f;
        #pragma unroll
        for (int i = 0; i < 8; i++) s += g_meanpart[t][i];
        g_mean[t] = s * (1.0f / NE);
    }
}

__global__ void k_scatter() {
    int e = blockIdx.x * blockDim.x + threadIdx.x;
    if (e >= NE) return;
    int d = g_dst32[e];
    int pos = atomicAdd(&g_cur[d], 1);
    g_sorted[pos] = ((unsigned)g_src32[e] << 20) | (unsigned)e;
}

// ---------------- GEMM (f32x2 packed): h = x @ W, a_src, a_dst --------------
// (R4 version, proven: smem Wt padded stride 132 + per-warp xp staging)
__global__ void __launch_bounds__(256)
k_gemm(const float* __restrict__ x, const float* __restrict__ W,
       const float* __restrict__ attS, const float* __restrict__ attD) {
    __shared__ float  Wt[32 * 132];
    __shared__ float2 xp[8][4][128];

    int tid = threadIdx.x, wid = tid >> 5, lane = tid & 31;

    for (int i = tid; i < DIN * FF; i += 256) {
        int k = i >> 5, f = i & 31;
        Wt[f * 132 + k] = W[i];
    }

    size_t rowBase = (size_t)blockIdx.x * 64 + (size_t)wid * 8;
    const float* xg = x + rowBase * DIN;
    #pragma unroll
    for (int p = 0; p < 4; p++) {
        float4 r0 = ((const float4*)(xg + (2 * p + 0) * DIN))[lane];
        float4 r1 = ((const float4*)(xg + (2 * p + 1) * DIN))[lane];
        xp[wid][p][4 * lane + 0] = make_float2(r0.x, r1.x);
        xp[wid][p][4 * lane + 1] = make_float2(r0.y, r1.y);
        xp[wid][p][4 * lane + 2] = make_float2(r0.z, r1.z);
        xp[wid][p][4 * lane + 3] = make_float2(r0.w, r1.w);
    }
    __syncthreads();

    unsigned long long acc[4] = {0ull, 0ull, 0ull, 0ull};
    #pragma unroll 4
    for (int kc = 0; kc < 32; kc++) {
        float4 wf = *(const float4*)&Wt[lane * 132 + kc * 4];
        unsigned long long w0 = dup2(wf.x), w1 = dup2(wf.y);
        unsigned long long w2 = dup2(wf.z), w3 = dup2(wf.w);
        #pragma unroll
        for (int p = 0; p < 4; p++) {
            ulonglong2 u01 = *(const ulonglong2*)&xp[wid][p][4 * kc + 0];
            ulonglong2 u23 = *(const ulonglong2*)&xp[wid][p][4 * kc + 2];
            fma2(acc[p], u01.x, w0);
            fma2(acc[p], u01.y, w1);
            fma2(acc[p], u23.x, w2);
            fma2(acc[p], u23.y, w3);
        }
    }

    float aS = attS[lane], aD = attD[lane];
    float* hp = g_h + rowBase * FF;
    #pragma unroll
    for (int p = 0; p < 4; p++) {
        float lo, hi;
        unpack2(acc[p], lo, hi);
        hp[(2 * p + 0) * FF + lane] = lo;
        hp[(2 * p + 1) * FF + lane] = hi;
        float vs0 = lo * aS, vd0 = lo * aD, vs1 = hi * aS, vd1 = hi * aD;
        #pragma unroll
        for (int o = 16; o; o >>= 1) {
            vs0 += __shfl_xor_sync(0xFFFFFFFFu, vs0, o);
            vd0 += __shfl_xor_sync(0xFFFFFFFFu, vd0, o);
            vs1 += __shfl_xor_sync(0xFFFFFFFFu, vs1, o);
            vd1 += __shfl_xor_sync(0xFFFFFFFFu, vd1, o);
        }
        if (lane == 0) {
            g_asrc[rowBase + 2 * p + 0] = vs0;
            g_adst[rowBase + 2 * p + 0] = vd0;
            g_asrc[rowBase + 2 * p + 1] = vs1;
            g_adst[rowBase + 2 * p + 1] = vd1;
        }
    }
}

// ---------------- single-pass-per-edge, two L1-resident gather passes -------
__device__ __forceinline__ float lrelu(float a) {
    return fmaxf(a, 0.f) + 0.2f * fminf(a, 0.f);
}

__global__ void __launch_bounds__(256)
k_edge(const float* __restrict__ eattr, const float* __restrict__ bias) {
    int wid = threadIdx.x >> 5, lane = threadIdx.x & 31;
    int seg = blockIdx.x * 8 + wid;                 // 0 .. NB*NN-1
    int b = seg / NN, d = seg - b * NN;

    const float* asb = g_asrc + b * NN;
    const float* eab = eattr + (size_t)b * NE;
    const float* hb  = g_h + (size_t)b * NN * FF;
    float ad = g_adst[b * NN + d];
    float c = g_c;
    int lo = g_off[d], hi = g_off[d + 1];
    int q = lane & 7, g4 = lane >> 3;

    float4 acc = make_float4(0.f, 0.f, 0.f, 0.f);
    float ssum = 0.f;

    // Two passes over the (src-sorted) segment: pass 0 gathers rows < SPLIT,
    // pass 1 gathers rows >= SPLIT. Each pass's hot h-region is 128KB -> L1.
    // exp/eattr computed exactly once per edge (inactive lanes contribute 0).
    #pragma unroll 1
    for (int pass = 0; pass < 2; pass++) {
        for (int base = lo; base < hi; base += 32) {
            int m = hi - base;
            if (m > 32) m = 32;
            float ex = 0.f;
            int idx = 0;
            if (lane < m) {
                unsigned p = __ldcg(&g_sorted[base + lane]);
                int sA = p >> 20;
                if ((sA < SPLIT) == (pass == 0)) {
                    int eid = p & 0xFFFFFu;
                    ex = __expf(lrelu(asb[sA] + ad + c * __ldcg(&eab[eid])));
                    idx = sA * FF;
                }
            }
            ssum += ex;
            for (int g = 0; g < m; g += 8) {
                int j0 = g + g4, j1 = g + 4 + g4;
                float e0 = __shfl_sync(0xFFFFFFFFu, ex, j0);
                int   i0 = __shfl_sync(0xFFFFFFFFu, idx, j0);
                float e1 = __shfl_sync(0xFFFFFFFFu, ex, j1);
                int   i1 = __shfl_sync(0xFFFFFFFFu, idx, j1);
                if (e0 != 0.f) {                     // warp-uniform predicate
                    float4 v0 = *(const float4*)(hb + i0 + q * 4);
                    acc.x = fmaf(e0, v0.x, acc.x);
                    acc.y = fmaf(e0, v0.y, acc.y);
                    acc.z = fmaf(e0, v0.z, acc.z);
                    acc.w = fmaf(e0, v0.w, acc.w);
                }
                if (e1 != 0.f) {
                    float4 v1 = *(const float4*)(hb + i1 + q * 4);
                    acc.x = fmaf(e1, v1.x, acc.x);
                    acc.y = fmaf(e1, v1.y, acc.y);
                    acc.z = fmaf(e1, v1.z, acc.z);
                    acc.w = fmaf(e1, v1.w, acc.w);
                }
            }
        }
    }

    float exs = __expf(lrelu(asb[d] + ad + c * g_mean[b]));
    #pragma unroll
    for (int o = 16; o; o >>= 1) ssum += __shfl_xor_sync(0xFFFFFFFFu, ssum, o);
    float inv = 1.f / (ssum + exs);

    #pragma unroll
    for (int o = 8; o <= 16; o <<= 1) {
        acc.x += __shfl_xor_sync(0xFFFFFFFFu, acc.x, o);
        acc.y += __shfl_xor_sync(0xFFFFFFFFu, acc.y, o);
        acc.z += __shfl_xor_sync(0xFFFFFFFFu, acc.z, o);
        acc.w += __shfl_xor_sync(0xFFFFFFFFu, acc.w, o);
    }

    if (lane < 8) {
        float4 hs = __ldcg((const float4*)(hb + (size_t)d * FF + q * 4));
        float4 bq = *(const float4*)(bias + q * 4);
        float4 r;
        r.x = fmaf(exs, hs.x, acc.x) * inv + bq.x;
        r.y = fmaf(exs, hs.y, acc.y) * inv + bq.y;
        r.z = fmaf(exs, hs.z, acc.z) * inv + bq.z;
        r.w = fmaf(exs, hs.w, acc.w) * inv + bq.w;
        *(float4*)(g_rep + ((size_t)b * NN + d) * FF + q * 4) = r;
    }
}

// ---------------- regulon pooling: out[b,r] = rep[b,r] + sum rep[b,dst] -----
__global__ void __launch_bounds__(256)
k_pool(float* __restrict__ out) {
    int wid = threadIdx.x >> 5, lane = threadIdx.x & 31;
    int seg = blockIdx.x * 8 + wid;                 // 0 .. NB*NREG-1
    int b = seg / NREG, r = seg - b * NREG;
    int lo = g_soff[r], hi = g_soff[r + 1];
    const float* repb = g_rep + (size_t)b * NN * FF;
    int q = lane & 7, g4 = lane >> 3;

    float4 a0 = make_float4(0.f, 0.f, 0.f, 0.f);
    float4 a1 = make_float4(0.f, 0.f, 0.f, 0.f);

    for (int base = lo; base < hi; base += 32) {
        int m = hi - base;
        if (m > 32) m = 32;
        int idx = (lane < m) ? g_dst32[base + lane] * FF : -1;
        for (int g = 0; g < m; g += 8) {
            int i0 = __shfl_sync(0xFFFFFFFFu, idx, g + g4);
            int i1 = __shfl_sync(0xFFFFFFFFu, idx, g + 4 + g4);
            if (i0 >= 0) {
                float4 v = *(const float4*)(repb + i0 + q * 4);
                a0.x += v.x; a0.y += v.y; a0.z += v.z; a0.w += v.w;
            }
            if (i1 >= 0) {
                float4 v = *(const float4*)(repb + i1 + q * 4);
                a1.x += v.x; a1.y += v.y; a1.z += v.z; a1.w += v.w;
            }
        }
    }
    a0.x += a1.x; a0.y += a1.y; a0.z += a1.z; a0.w += a1.w;

    #pragma unroll
    for (int o = 8; o <= 16; o <<= 1) {
        a0.x += __shfl_xor_sync(0xFFFFFFFFu, a0.x, o);
        a0.y += __shfl_xor_sync(0xFFFFFFFFu, a0.y, o);
        a0.z += __shfl_xor_sync(0xFFFFFFFFu, a0.z, o);
        a0.w += __shfl_xor_sync(0xFFFFFFFFu, a0.w, o);
    }

    if (lane < 8) {
        float4 self = *(const float4*)(repb + (size_t)r * FF + q * 4);
        float4 o4;
        o4.x = a0.x + self.x;
        o4.y = a0.y + self.y;
        o4.z = a0.z + self.z;
        o4.w = a0.w + self.w;
        *(float4*)(out + ((size_t)b * NREG + r) * FF + q * 4) = o4;
    }
}

// ---------------- launch ---------------------------------------------------
extern "C" void kernel_launch(void* const* d_in, const int* in_sizes, int n_in,
                              void* d_out, int out_size) {
    const float* x        = (const float*)d_in[0];
    const float* edgeattr = (const float*)d_in[1];
    const float* W        = (const float*)d_in[2];
    const float* att_src  = (const float*)d_in[3];
    const float* att_dst  = (const float*)d_in[4];
    const float* lin_edge = (const float*)d_in[5];
    const float* att_edge = (const float*)d_in[6];
    const float* bias     = (const float*)d_in[7];
    const void*  esrc     = d_in[8];
    const void*  edst     = d_in[9];
    float* out = (float*)d_out;

    k_prep<<<dim3(8, NB), 256>>>(edgeattr, lin_edge, att_edge, (const int*)edst);
    k_convert<<<NE / 256, 256>>>(esrc, edst);
    k_scan<<<1, 1024>>>();
    k_gemm<<<(NB * NN) / 64, 256>>>(x, W, att_src, att_dst);   // 4th: profiled
    k_scatter<<<NE / 256, 256>>>();
    k_edge<<<(NB * NN) / 8, 256>>>(edgeattr, bias);
    k_pool<<<(NB * NREG) / 8, 256>>>(out);
}

// round 8
// speedup vs baseline: 1.3752x; 1.1813x over previous
#include <cuda_runtime.h>
#include <cstdint>

#define NB   16
#define NN   20000
#define NE   640000
#define NREG 2000
#define DIN  128
#define FF   32

// ---------------- scratch (device globals; no allocation allowed) ----------
__device__ float    g_h[(size_t)NB * NN * FF];       // 40.96 MB
__device__ float    g_rep[(size_t)NB * NN * FF];     // 40.96 MB
__device__ float    g_asrc[NB * NN];
__device__ float    g_adst[NB * NN];
__device__ int      g_src32[NE];
__device__ int      g_dst32[NE];
__device__ int      g_cnt[NN];
__device__ int      g_off[NN + 1];
__device__ int      g_cur[NN];
__device__ unsigned g_sorted[NE];                    // (src<<20)|eid
__device__ int      g_soff[NREG + 1];
__device__ float    g_meanpart[NB][8];
__device__ float    g_mean[NB];
__device__ float    g_c;
__device__ int      g_is64;

// ---------------- f32x2 helpers ---------------------------------------------
__device__ __forceinline__ void fma2(unsigned long long& d,
                                     unsigned long long a,
                                     unsigned long long b) {
    asm("fma.rn.f32x2 %0, %1, %2, %0;" : "+l"(d) : "l"(a), "l"(b));
}
__device__ __forceinline__ unsigned long long dup2(float w) {
    unsigned long long r;
    asm("mov.b64 %0, {%1, %1};" : "=l"(r) : "f"(w));
    return r;
}
__device__ __forceinline__ void unpack2(unsigned long long v, float& lo, float& hi) {
    asm("mov.b64 {%0, %1}, %2;" : "=f"(lo), "=f"(hi) : "l"(v));
}

// ---------------- prep: zero cnt, mean partials, scalar c, dtype detect -----
__global__ void k_prep(const float* __restrict__ eattr,
                       const float* __restrict__ lin_edge,
                       const float* __restrict__ att_edge,
                       const int* __restrict__ edge_raw) {
    int tid = threadIdx.x, bx = blockIdx.x, by = blockIdx.y;
    int lane = tid & 31, wid = tid >> 5;

    int id = (by * 8 + bx) * 256 + tid;
    if (id < NN) g_cnt[id] = 0;

    if (bx == 0 && by == 0) {
        if (wid == 0) {
            int any = 0;
            for (int i = lane; i < 1024; i += 32)
                if ((i & 1) && edge_raw[i] != 0) any = 1;
            #pragma unroll
            for (int o = 16; o; o >>= 1) any |= __shfl_xor_sync(0xFFFFFFFFu, any, o);
            if (lane == 0) g_is64 = !any;
        } else if (wid == 1) {
            float p = lin_edge[lane] * att_edge[lane];
            #pragma unroll
            for (int o = 16; o; o >>= 1) p += __shfl_xor_sync(0xFFFFFFFFu, p, o);
            if (lane == 0) g_c = p;
        }
    }

    const float* p = eattr + (size_t)by * NE;
    float s = 0.f;
    for (int i = bx * 256 + tid; i < NE; i += 8 * 256) s += p[i];
    __shared__ float sm[8];
    #pragma unroll
    for (int o = 16; o; o >>= 1) s += __shfl_xor_sync(0xFFFFFFFFu, s, o);
    if (lane == 0) sm[wid] = s;
    __syncthreads();
    if (wid == 0) {
        s = (lane < 8) ? sm[lane] : 0.f;
        #pragma unroll
        for (int o = 4; o; o >>= 1) s += __shfl_xor_sync(0xFFFFFFFFu, s, o);
        if (lane == 0) g_meanpart[by][bx] = s;
    }
}

// ---------------- convert indices + histogram -------------------------------
__global__ void k_convert(const void* __restrict__ srcv,
                          const void* __restrict__ dstv) {
    int e = blockIdx.x * blockDim.x + threadIdx.x;
    if (e >= NE) return;
    int s, d;
    if (g_is64) {
        s = (int)((const long long*)srcv)[e];
        d = (int)((const long long*)dstv)[e];
    } else {
        s = ((const int*)srcv)[e];
        d = ((const int*)dstv)[e];
    }
    g_src32[e] = s;
    g_dst32[e] = d;
    atomicAdd(&g_cnt[d], 1);
}

// ---------------- scan + soff + mean finalize (single block, 1024 thr) ------
__global__ void k_scan() {
    __shared__ int tot[1024];
    int t = threadIdx.x;
    int base = t * 20;
    int loc[20];
    int run = 0;
    #pragma unroll
    for (int i = 0; i < 20; i++) {
        int idx = base + i;
        int v = (idx < NN) ? g_cnt[idx] : 0;
        loc[i] = run;
        run += v;
    }
    tot[t] = run;
    __syncthreads();
    for (int off = 1; off < 1024; off <<= 1) {
        int v = (t >= off) ? tot[t - off] : 0;
        __syncthreads();
        tot[t] += v;
        __syncthreads();
    }
    int excl = tot[t] - run;
    #pragma unroll
    for (int i = 0; i < 20; i++) {
        int idx = base + i;
        if (idx < NN) {
            int o = excl + loc[i];
            g_off[idx] = o;
            g_cur[idx] = o;
        }
    }
    if (t == 1023) g_off[NN] = tot[1023];

    for (int r = t; r <= NREG; r += 1024) {
        int lo = 0, hi = NE;
        while (lo < hi) {
            int mid = (lo + hi) >> 1;
            if (g_src32[mid] < r) lo = mid + 1; else hi = mid;
        }
        g_soff[r] = lo;
    }

    if (t < NB) {
        float s = 0.f;
        #pragma unroll
        for (int i = 0; i < 8; i++) s += g_meanpart[t][i];
        g_mean[t] = s * (1.0f / NE);
    }
}

__global__ void k_scatter() {
    int e = blockIdx.x * blockDim.x + threadIdx.x;
    if (e >= NE) return;
    int d = g_dst32[e];
    int pos = atomicAdd(&g_cur[d], 1);
    g_sorted[pos] = ((unsigned)g_src32[e] << 20) | (unsigned)e;
}

// ---------------- GEMM v3: lane = row, features packed in 16 f32x2 ---------
// Per kj: 1 rotated LDS.128 for own-row x + 8 broadcast LDS.128 of W rows
// feed 64 fma2 per lane -> fma-pipe bound (~38us floor).
__global__ void __launch_bounds__(64)
k_gemm(const float* __restrict__ x, const float* __restrict__ W,
       const float* __restrict__ attS, const float* __restrict__ attD) {
    __shared__ float Ws[DIN * FF];        // 16 KB, plain row-major [k][f]
    __shared__ float xs[2][32][128];      // 32 KB, per-warp, rotated rows

    int tid = threadIdx.x, wid = tid >> 5, lane = tid & 31;

    // stage W (both warps cooperate)
    #pragma unroll
    for (int i = 0; i < 16; i++)
        ((float4*)Ws)[tid + 64 * i] = ((const float4*)W)[tid + 64 * i];
    __syncthreads();

    size_t rowBase = (size_t)blockIdx.x * 64 + (size_t)wid * 32;
    const float* xg = x + rowBase * DIN;

    // stage this warp's 32 rows, rotated by 4*r floats (bank-conflict-free)
    #pragma unroll 4
    for (int r = 0; r < 32; r++) {
        float4 v = ((const float4*)(xg + r * DIN))[lane];
        int c = (4 * lane + 4 * r) & 127;
        *(float4*)&xs[wid][r][c] = v;
    }
    __syncwarp();

    unsigned long long acc[16];
    #pragma unroll
    for (int j = 0; j < 16; j++) acc[j] = 0ull;

    #pragma unroll 2
    for (int kj = 0; kj < 32; kj++) {
        int c = (4 * kj + 4 * lane) & 127;
        float4 xv = *(const float4*)&xs[wid][lane][c];   // k = 4kj..4kj+3
        float xk0 = xv.x, xk1 = xv.y, xk2 = xv.z, xk3 = xv.w;
        const float* wbase = Ws + 4 * kj * FF;
        #pragma unroll
        for (int dk = 0; dk < 4; dk++) {
            float xkv = dk == 0 ? xk0 : dk == 1 ? xk1 : dk == 2 ? xk2 : xk3;
            unsigned long long xb = dup2(xkv);
            const ulonglong2* wrow = (const ulonglong2*)(wbase + dk * FF);
            #pragma unroll
            for (int jj = 0; jj < 8; jj++) {
                ulonglong2 w2 = wrow[jj];                // broadcast LDS.128
                fma2(acc[2 * jj + 0], w2.x, xb);
                fma2(acc[2 * jj + 1], w2.y, xb);
            }
        }
    }

    // epilogue: lane owns full output row
    size_t row = rowBase + lane;
    float o[32];
    #pragma unroll
    for (int j = 0; j < 16; j++) unpack2(acc[j], o[2 * j], o[2 * j + 1]);

    float* hp = g_h + row * FF;
    float vs = 0.f, vd = 0.f;
    #pragma unroll
    for (int t = 0; t < 8; t++) {
        float4 ov = make_float4(o[4 * t], o[4 * t + 1], o[4 * t + 2], o[4 * t + 3]);
        ((float4*)hp)[t] = ov;
        float4 a4 = __ldg(&((const float4*)attS)[t]);
        float4 d4 = __ldg(&((const float4*)attD)[t]);
        vs = fmaf(ov.x, a4.x, fmaf(ov.y, a4.y, fmaf(ov.z, a4.z, fmaf(ov.w, a4.w, vs))));
        vd = fmaf(ov.x, d4.x, fmaf(ov.y, d4.y, fmaf(ov.z, d4.z, fmaf(ov.w, d4.w, vd))));
    }
    g_asrc[row] = vs;
    g_adst[row] = vd;
}

// ---------------- single-pass per-(b,dst) softmax + aggregation (R4) --------
__device__ __forceinline__ float lrelu(float a) {
    return fmaxf(a, 0.f) + 0.2f * fminf(a, 0.f);
}

__global__ void __launch_bounds__(256)
k_edge(const float* __restrict__ eattr, const float* __restrict__ bias) {
    int wid = threadIdx.x >> 5, lane = threadIdx.x & 31;
    int seg = blockIdx.x * 8 + wid;                 // 0 .. NB*NN-1
    int b = seg / NN, d = seg - b * NN;

    const float* asb = g_asrc + b * NN;
    const float* eab = eattr + (size_t)b * NE;
    const float* hb  = g_h + (size_t)b * NN * FF;
    float ad = g_adst[b * NN + d];
    float c = g_c;
    int lo = g_off[d], hi = g_off[d + 1];
    int q = lane & 7, g4 = lane >> 3;

    float4 acc = make_float4(0.f, 0.f, 0.f, 0.f);
    float ssum = 0.f;

    for (int base = lo; base < hi; base += 32) {
        int m = hi - base;
        if (m > 32) m = 32;
        float ex = 0.f;
        int idx = d * FF;                            // safe default row
        if (lane < m) {
            unsigned p = g_sorted[base + lane];
            int sA = p >> 20;
            int eid = p & 0xFFFFFu;
            ex = __expf(lrelu(asb[sA] + ad + c * __ldg(&eab[eid])));
            idx = sA * FF;
        }
        ssum += ex;
        for (int g = 0; g < m; g += 8) {
            int j0 = g + g4, j1 = g + 4 + g4;
            float e0 = __shfl_sync(0xFFFFFFFFu, ex, j0);
            int   i0 = __shfl_sync(0xFFFFFFFFu, idx, j0);
            float e1 = __shfl_sync(0xFFFFFFFFu, ex, j1);
            int   i1 = __shfl_sync(0xFFFFFFFFu, idx, j1);
            float4 v0 = *(const float4*)(hb + i0 + q * 4);
            float4 v1 = *(const float4*)(hb + i1 + q * 4);
            acc.x = fmaf(e0, v0.x, acc.x);
            acc.y = fmaf(e0, v0.y, acc.y);
            acc.z = fmaf(e0, v0.z, acc.z);
            acc.w = fmaf(e0, v0.w, acc.w);
            acc.x = fmaf(e1, v1.x, acc.x);
            acc.y = fmaf(e1, v1.y, acc.y);
            acc.z = fmaf(e1, v1.z, acc.z);
            acc.w = fmaf(e1, v1.w, acc.w);
        }
    }

    float exs = __expf(lrelu(asb[d] + ad + c * g_mean[b]));
    #pragma unroll
    for (int o = 16; o; o >>= 1) ssum += __shfl_xor_sync(0xFFFFFFFFu, ssum, o);
    float inv = 1.f / (ssum + exs);

    #pragma unroll
    for (int o = 8; o <= 16; o <<= 1) {
        acc.x += __shfl_xor_sync(0xFFFFFFFFu, acc.x, o);
        acc.y += __shfl_xor_sync(0xFFFFFFFFu, acc.y, o);
        acc.z += __shfl_xor_sync(0xFFFFFFFFu, acc.z, o);
        acc.w += __shfl_xor_sync(0xFFFFFFFFu, acc.w, o);
    }

    if (lane < 8) {
        float4 hs = *(const float4*)(hb + (size_t)d * FF + q * 4);
        float4 bq = *(const float4*)(bias + q * 4);
        float4 r;
        r.x = fmaf(exs, hs.x, acc.x) * inv + bq.x;
        r.y = fmaf(exs, hs.y, acc.y) * inv + bq.y;
        r.z = fmaf(exs, hs.z, acc.z) * inv + bq.z;
        r.w = fmaf(exs, hs.w, acc.w) * inv + bq.w;
        *(float4*)(g_rep + ((size_t)b * NN + d) * FF + q * 4) = r;
    }
}

// ---------------- regulon pooling: out[b,r] = rep[b,r] + sum rep[b,dst] -----
__global__ void __launch_bounds__(256)
k_pool(float* __restrict__ out) {
    int wid = threadIdx.x >> 5, lane = threadIdx.x & 31;
    int seg = blockIdx.x * 8 + wid;                 // 0 .. NB*NREG-1
    int b = seg / NREG, r = seg - b * NREG;
    int lo = g_soff[r], hi = g_soff[r + 1];
    const float* repb = g_rep + (size_t)b * NN * FF;
    int q = lane & 7, g4 = lane >> 3;

    float4 a0 = make_float4(0.f, 0.f, 0.f, 0.f);
    float4 a1 = make_float4(0.f, 0.f, 0.f, 0.f);

    for (int base = lo; base < hi; base += 32) {
        int m = hi - base;
        if (m > 32) m = 32;
        int idx = (lane < m) ? g_dst32[base + lane] * FF : -1;
        for (int g = 0; g < m; g += 8) {
            int i0 = __shfl_sync(0xFFFFFFFFu, idx, g + g4);
            int i1 = __shfl_sync(0xFFFFFFFFu, idx, g + 4 + g4);
            if (i0 >= 0) {
                float4 v = *(const float4*)(repb + i0 + q * 4);
                a0.x += v.x; a0.y += v.y; a0.z += v.z; a0.w += v.w;
            }
            if (i1 >= 0) {
                float4 v = *(const float4*)(repb + i1 + q * 4);
                a1.x += v.x; a1.y += v.y; a1.z += v.z; a1.w += v.w;
            }
        }
    }
    a0.x += a1.x; a0.y += a1.y; a0.z += a1.z; a0.w += a1.w;

    #pragma unroll
    for (int o = 8; o <= 16; o <<= 1) {
        a0.x += __shfl_xor_sync(0xFFFFFFFFu, a0.x, o);
        a0.y += __shfl_xor_sync(0xFFFFFFFFu, a0.y, o);
        a0.z += __shfl_xor_sync(0xFFFFFFFFu, a0.z, o);
        a0.w += __shfl_xor_sync(0xFFFFFFFFu, a0.w, o);
    }

    if (lane < 8) {
        float4 self = *(const float4*)(repb + (size_t)r * FF + q * 4);
        float4 o4;
        o4.x = a0.x + self.x;
        o4.y = a0.y + self.y;
        o4.z = a0.z + self.z;
        o4.w = a0.w + self.w;
        *(float4*)(out + ((size_t)b * NREG + r) * FF + q * 4) = o4;
    }
}

// ---------------- launch ---------------------------------------------------
extern "C" void kernel_launch(void* const* d_in, const int* in_sizes, int n_in,
                              void* d_out, int out_size) {
    const float* x        = (const float*)d_in[0];
    const float* edgeattr = (const float*)d_in[1];
    const float* W        = (const float*)d_in[2];
    const float* att_src  = (const float*)d_in[3];
    const float* att_dst  = (const float*)d_in[4];
    const float* lin_edge = (const float*)d_in[5];
    const float* att_edge = (const float*)d_in[6];
    const float* bias     = (const float*)d_in[7];
    const void*  esrc     = d_in[8];
    const void*  edst     = d_in[9];
    float* out = (float*)d_out;

    k_prep<<<dim3(8, NB), 256>>>(edgeattr, lin_edge, att_edge, (const int*)edst);
    k_convert<<<NE / 256, 256>>>(esrc, edst);
    k_scan<<<1, 1024>>>();
    k_gemm<<<(NB * NN) / 64, 64>>>(x, W, att_src, att_dst);   // 4th: profiled
    k_scatter<<<NE / 256, 256>>>();
    k_edge<<<(NB * NN) / 8, 256>>>(edgeattr, bias);
    k_pool<<<(NB * NREG) / 8, 256>>>(out);
}

// round 9
// speedup vs baseline: 1.4293x; 1.0393x over previous
#include <cuda_runtime.h>
#include <cstdint>

#define NB   16
#define NN   20000
#define NE   640000
#define NREG 2000
#define DIN  128
#define FF   32

// ---------------- scratch (device globals; no allocation allowed) ----------
__device__ float    g_h[(size_t)NB * NN * FF];       // 40.96 MB
__device__ float    g_rep[(size_t)NB * NN * FF];     // 40.96 MB
__device__ float    g_asrc[NB * NN];
__device__ float    g_adst[NB * NN];
__device__ int      g_src32[NE];
__device__ int      g_dst32[NE];
__device__ int      g_cnt[NN];
__device__ int      g_off[NN + 1];
__device__ int      g_cur[NN];
__device__ unsigned g_sorted[NE];                    // (src<<20)|eid
__device__ int      g_soff[NREG + 1];
__device__ float    g_meanpart[NB][8];
__device__ float    g_mean[NB];
__device__ float    g_c;
__device__ int      g_is64;

// ---------------- f32x2 helpers ---------------------------------------------
__device__ __forceinline__ void fma2(unsigned long long& d,
                                     unsigned long long a,
                                     unsigned long long b) {
    asm("fma.rn.f32x2 %0, %1, %2, %0;" : "+l"(d) : "l"(a), "l"(b));
}
__device__ __forceinline__ unsigned long long dup2(float w) {
    unsigned long long r;
    asm("mov.b64 %0, {%1, %1};" : "=l"(r) : "f"(w));
    return r;
}
__device__ __forceinline__ void unpack2(unsigned long long v, float& lo, float& hi) {
    asm("mov.b64 {%0, %1}, %2;" : "=f"(lo), "=f"(hi) : "l"(v));
}

// ---------------- prep: zero cnt, mean partials, scalar c, dtype detect -----
__global__ void k_prep(const float* __restrict__ eattr,
                       const float* __restrict__ lin_edge,
                       const float* __restrict__ att_edge,
                       const int* __restrict__ edge_raw) {
    int tid = threadIdx.x, bx = blockIdx.x, by = blockIdx.y;
    int lane = tid & 31, wid = tid >> 5;

    int id = (by * 8 + bx) * 256 + tid;
    if (id < NN) g_cnt[id] = 0;

    if (bx == 0 && by == 0) {
        if (wid == 0) {
            int any = 0;
            for (int i = lane; i < 1024; i += 32)
                if ((i & 1) && edge_raw[i] != 0) any = 1;
            #pragma unroll
            for (int o = 16; o; o >>= 1) any |= __shfl_xor_sync(0xFFFFFFFFu, any, o);
            if (lane == 0) g_is64 = !any;
        } else if (wid == 1) {
            float p = lin_edge[lane] * att_edge[lane];
            #pragma unroll
            for (int o = 16; o; o >>= 1) p += __shfl_xor_sync(0xFFFFFFFFu, p, o);
            if (lane == 0) g_c = p;
        }
    }

    const float* p = eattr + (size_t)by * NE;
    float s = 0.f;
    for (int i = bx * 256 + tid; i < NE; i += 8 * 256) s += p[i];
    __shared__ float sm[8];
    #pragma unroll
    for (int o = 16; o; o >>= 1) s += __shfl_xor_sync(0xFFFFFFFFu, s, o);
    if (lane == 0) sm[wid] = s;
    __syncthreads();
    if (wid == 0) {
        s = (lane < 8) ? sm[lane] : 0.f;
        #pragma unroll
        for (int o = 4; o; o >>= 1) s += __shfl_xor_sync(0xFFFFFFFFu, s, o);
        if (lane == 0) g_meanpart[by][bx] = s;
    }
}

// ---------------- convert indices + histogram -------------------------------
__global__ void k_convert(const void* __restrict__ srcv,
                          const void* __restrict__ dstv) {
    int e = blockIdx.x * blockDim.x + threadIdx.x;
    if (e >= NE) return;
    int s, d;
    if (g_is64) {
        s = (int)((const long long*)srcv)[e];
        d = (int)((const long long*)dstv)[e];
    } else {
        s = ((const int*)srcv)[e];
        d = ((const int*)dstv)[e];
    }
    g_src32[e] = s;
    g_dst32[e] = d;
    atomicAdd(&g_cnt[d], 1);
}

// ---------------- scan + soff + mean finalize (single block, 1024 thr) ------
__global__ void k_scan() {
    __shared__ int tot[1024];
    int t = threadIdx.x;
    int base = t * 20;
    int loc[20];
    int run = 0;
    #pragma unroll
    for (int i = 0; i < 20; i++) {
        int idx = base + i;
        int v = (idx < NN) ? g_cnt[idx] : 0;
        loc[i] = run;
        run += v;
    }
    tot[t] = run;
    __syncthreads();
    for (int off = 1; off < 1024; off <<= 1) {
        int v = (t >= off) ? tot[t - off] : 0;
        __syncthreads();
        tot[t] += v;
        __syncthreads();
    }
    int excl = tot[t] - run;
    #pragma unroll
    for (int i = 0; i < 20; i++) {
        int idx = base + i;
        if (idx < NN) {
            int o = excl + loc[i];
            g_off[idx] = o;
            g_cur[idx] = o;
        }
    }
    if (t == 1023) g_off[NN] = tot[1023];

    for (int r = t; r <= NREG; r += 1024) {
        int lo = 0, hi = NE;
        while (lo < hi) {
            int mid = (lo + hi) >> 1;
            if (g_src32[mid] < r) lo = mid + 1; else hi = mid;
        }
        g_soff[r] = lo;
    }

    if (t < NB) {
        float s = 0.f;
        #pragma unroll
        for (int i = 0; i < 8; i++) s += g_meanpart[t][i];
        g_mean[t] = s * (1.0f / NE);
    }
}

__global__ void k_scatter() {
    int e = blockIdx.x * blockDim.x + threadIdx.x;
    if (e >= NE) return;
    int d = g_dst32[e];
    int pos = atomicAdd(&g_cur[d], 1);
    g_sorted[pos] = ((unsigned)g_src32[e] << 20) | (unsigned)e;
}

// ---------------- GEMM v4: lane = row, K-chunked staging, 4 warps/block ----
// Per K-chunk (64): stage 8KB/warp rotated x, then 16 kj-steps of
// (1 rotated LDS.128 own-row x) + (8 broadcast LDS.128 W rows) -> 64 fma2.
__global__ void __launch_bounds__(128, 4)
k_gemm(const float* __restrict__ x, const float* __restrict__ W,
       const float* __restrict__ attS, const float* __restrict__ attD) {
    __shared__ float Ws[DIN * FF];        // 16 KB, row-major [k][f]
    __shared__ float xs[4][32][64];       // 32 KB, per-warp, rotated chunks

    int tid = threadIdx.x, wid = tid >> 5, lane = tid & 31;

    // stage W (all 128 threads)
    #pragma unroll
    for (int i = 0; i < 8; i++)
        ((float4*)Ws)[tid + 128 * i] = ((const float4*)W)[tid + 128 * i];
    __syncthreads();

    size_t rowBase = (size_t)blockIdx.x * 128 + (size_t)wid * 32;
    const float* xg = x + rowBase * DIN;

    unsigned long long acc[16];
    #pragma unroll
    for (int j = 0; j < 16; j++) acc[j] = 0ull;

    #pragma unroll
    for (int kc = 0; kc < 2; kc++) {
        // stage this warp's 32 rows x 64 floats, rotated by row (float4 units)
        #pragma unroll
        for (int i = 0; i < 16; i++) {
            int idx = i * 32 + lane;
            int row = idx >> 4, seg = idx & 15;
            float4 v = ((const float4*)(xg + row * DIN + kc * 64))[seg];
            ((float4*)&xs[wid][row][0])[(seg + row) & 15] = v;
        }
        __syncwarp();

        #pragma unroll 2
        for (int kj = 0; kj < 16; kj++) {
            float4 xv = ((const float4*)&xs[wid][lane][0])[(kj + lane) & 15];
            const float* wbase = Ws + (kc * 64 + kj * 4) * FF;
            #pragma unroll
            for (int dk = 0; dk < 4; dk++) {
                float xkv = dk == 0 ? xv.x : dk == 1 ? xv.y : dk == 2 ? xv.z : xv.w;
                unsigned long long xb = dup2(xkv);
                const ulonglong2* wrow = (const ulonglong2*)(wbase + dk * FF);
                #pragma unroll
                for (int jj = 0; jj < 8; jj++) {
                    ulonglong2 w2 = wrow[jj];            // broadcast LDS.128
                    fma2(acc[2 * jj + 0], w2.x, xb);
                    fma2(acc[2 * jj + 1], w2.y, xb);
                }
            }
        }
        __syncwarp();
    }

    // epilogue: lane owns full output row
    size_t row = rowBase + lane;
    float o[32];
    #pragma unroll
    for (int j = 0; j < 16; j++) unpack2(acc[j], o[2 * j], o[2 * j + 1]);

    float* hp = g_h + row * FF;
    float vs = 0.f, vd = 0.f;
    #pragma unroll
    for (int t = 0; t < 8; t++) {
        float4 ov = make_float4(o[4 * t], o[4 * t + 1], o[4 * t + 2], o[4 * t + 3]);
        ((float4*)hp)[t] = ov;
        float4 a4 = __ldg(&((const float4*)attS)[t]);
        float4 d4 = __ldg(&((const float4*)attD)[t]);
        vs = fmaf(ov.x, a4.x, fmaf(ov.y, a4.y, fmaf(ov.z, a4.z, fmaf(ov.w, a4.w, vs))));
        vd = fmaf(ov.x, d4.x, fmaf(ov.y, d4.y, fmaf(ov.z, d4.z, fmaf(ov.w, d4.w, vd))));
    }
    g_asrc[row] = vs;
    g_adst[row] = vd;
}

// ---------------- single-pass per-(b,dst) softmax + aggregation (R4) --------
__device__ __forceinline__ float lrelu(float a) {
    return fmaxf(a, 0.f) + 0.2f * fminf(a, 0.f);
}

__global__ void __launch_bounds__(256)
k_edge(const float* __restrict__ eattr, const float* __restrict__ bias) {
    int wid = threadIdx.x >> 5, lane = threadIdx.x & 31;
    int seg = blockIdx.x * 8 + wid;                 // 0 .. NB*NN-1
    int b = seg / NN, d = seg - b * NN;

    const float* asb = g_asrc + b * NN;
    const float* eab = eattr + (size_t)b * NE;
    const float* hb  = g_h + (size_t)b * NN * FF;
    float ad = g_adst[b * NN + d];
    float c = g_c;
    int lo = g_off[d], hi = g_off[d + 1];
    int q = lane & 7, g4 = lane >> 3;

    float4 acc = make_float4(0.f, 0.f, 0.f, 0.f);
    float ssum = 0.f;

    for (int base = lo; base < hi; base += 32) {
        int m = hi - base;
        if (m > 32) m = 32;
        float ex = 0.f;
        int idx = d * FF;                            // safe default row
        if (lane < m) {
            unsigned p = g_sorted[base + lane];
            int sA = p >> 20;
            int eid = p & 0xFFFFFu;
            ex = __expf(lrelu(asb[sA] + ad + c * __ldg(&eab[eid])));
            idx = sA * FF;
        }
        ssum += ex;
        for (int g = 0; g < m; g += 8) {
            int j0 = g + g4, j1 = g + 4 + g4;
            float e0 = __shfl_sync(0xFFFFFFFFu, ex, j0);
            int   i0 = __shfl_sync(0xFFFFFFFFu, idx, j0);
            float e1 = __shfl_sync(0xFFFFFFFFu, ex, j1);
            int   i1 = __shfl_sync(0xFFFFFFFFu, idx, j1);
            float4 v0 = *(const float4*)(hb + i0 + q * 4);
            float4 v1 = *(const float4*)(hb + i1 + q * 4);
            acc.x = fmaf(e0, v0.x, acc.x);
            acc.y = fmaf(e0, v0.y, acc.y);
            acc.z = fmaf(e0, v0.z, acc.z);
            acc.w = fmaf(e0, v0.w, acc.w);
            acc.x = fmaf(e1, v1.x, acc.x);
            acc.y = fmaf(e1, v1.y, acc.y);
            acc.z = fmaf(e1, v1.z, acc.z);
            acc.w = fmaf(e1, v1.w, acc.w);
        }
    }

    float exs = __expf(lrelu(asb[d] + ad + c * g_mean[b]));
    #pragma unroll
    for (int o = 16; o; o >>= 1) ssum += __shfl_xor_sync(0xFFFFFFFFu, ssum, o);
    float inv = 1.f / (ssum + exs);

    #pragma unroll
    for (int o = 8; o <= 16; o <<= 1) {
        acc.x += __shfl_xor_sync(0xFFFFFFFFu, acc.x, o);
        acc.y += __shfl_xor_sync(0xFFFFFFFFu, acc.y, o);
        acc.z += __shfl_xor_sync(0xFFFFFFFFu, acc.z, o);
        acc.w += __shfl_xor_sync(0xFFFFFFFFu, acc.w, o);
    }

    if (lane < 8) {
        float4 hs = *(const float4*)(hb + (size_t)d * FF + q * 4);
        float4 bq = *(const float4*)(bias + q * 4);
        float4 r;
        r.x = fmaf(exs, hs.x, acc.x) * inv + bq.x;
        r.y = fmaf(exs, hs.y, acc.y) * inv + bq.y;
        r.z = fmaf(exs, hs.z, acc.z) * inv + bq.z;
        r.w = fmaf(exs, hs.w, acc.w) * inv + bq.w;
        *(float4*)(g_rep + ((size_t)b * NN + d) * FF + q * 4) = r;
    }
}

// ---------------- regulon pooling: out[b,r] = rep[b,r] + sum rep[b,dst] -----
__global__ void __launch_bounds__(256)
k_pool(float* __restrict__ out) {
    int wid = threadIdx.x >> 5, lane = threadIdx.x & 31;
    int seg = blockIdx.x * 8 + wid;                 // 0 .. NB*NREG-1
    int b = seg / NREG, r = seg - b * NREG;
    int lo = g_soff[r], hi = g_soff[r + 1];
    const float* repb = g_rep + (size_t)b * NN * FF;
    int q = lane & 7, g4 = lane >> 3;

    float4 a0 = make_float4(0.f, 0.f, 0.f, 0.f);
    float4 a1 = make_float4(0.f, 0.f, 0.f, 0.f);

    for (int base = lo; base < hi; base += 32) {
        int m = hi - base;
        if (m > 32) m = 32;
        int idx = (lane < m) ? g_dst32[base + lane] * FF : -1;
        for (int g = 0; g < m; g += 8) {
            int i0 = __shfl_sync(0xFFFFFFFFu, idx, g + g4);
            int i1 = __shfl_sync(0xFFFFFFFFu, idx, g + 4 + g4);
            if (i0 >= 0) {
                float4 v = *(const float4*)(repb + i0 + q * 4);
                a0.x += v.x; a0.y += v.y; a0.z += v.z; a0.w += v.w;
            }
            if (i1 >= 0) {
                float4 v = *(const float4*)(repb + i1 + q * 4);
                a1.x += v.x; a1.y += v.y; a1.z += v.z; a1.w += v.w;
            }
        }
    }
    a0.x += a1.x; a0.y += a1.y; a0.z += a1.z; a0.w += a1.w;

    #pragma unroll
    for (int o = 8; o <= 16; o <<= 1) {
        a0.x += __shfl_xor_sync(0xFFFFFFFFu, a0.x, o);
        a0.y += __shfl_xor_sync(0xFFFFFFFFu, a0.y, o);
        a0.z += __shfl_xor_sync(0xFFFFFFFFu, a0.z, o);
        a0.w += __shfl_xor_sync(0xFFFFFFFFu, a0.w, o);
    }

    if (lane < 8) {
        float4 self = *(const float4*)(repb + (size_t)r * FF + q * 4);
        float4 o4;
        o4.x = a0.x + self.x;
        o4.y = a0.y + self.y;
        o4.z = a0.z + self.z;
        o4.w = a0.w + self.w;
        *(float4*)(out + ((size_t)b * NREG + r) * FF + q * 4) = o4;
    }
}

// ---------------- launch ---------------------------------------------------
extern "C" void kernel_launch(void* const* d_in, const int* in_sizes, int n_in,
                              void* d_out, int out_size) {
    const float* x        = (const float*)d_in[0];
    const float* edgeattr = (const float*)d_in[1];
    const float* W        = (const float*)d_in[2];
    const float* att_src  = (const float*)d_in[3];
    const float* att_dst  = (const float*)d_in[4];
    const float* lin_edge = (const float*)d_in[5];
    const float* att_edge = (const float*)d_in[6];
    const float* bias     = (const float*)d_in[7];
    const void*  esrc     = d_in[8];
    const void*  edst     = d_in[9];
    float* out = (float*)d_out;

    k_prep<<<dim3(8, NB), 256>>>(edgeattr, lin_edge, att_edge, (const int*)edst);
    k_convert<<<NE / 256, 256>>>(esrc, edst);
    k_scan<<<1, 1024>>>();
    k_gemm<<<(NB * NN) / 128, 128>>>(x, W, att_src, att_dst);  // 4th: profiled
    k_scatter<<<NE / 256, 256>>>();
    k_edge<<<(NB * NN) / 8, 256>>>(edgeattr, bias);
    k_pool<<<(NB * NREG) / 8, 256>>>(out);
}